// round 13
// baseline (speedup 1.0000x reference)
#include <cuda_runtime.h>
#include <cstdint>

// ---------------------------------------------------------------------------
// Problem constants
// ---------------------------------------------------------------------------
constexpr int B_   = 4;
constexpr int C_   = 256;
constexpr int H_   = 64;
constexpr int W_   = 64;
constexpr int Co_  = 256;
constexpr int HW_  = 64 * 64;           // 4096
constexpr int F_   = C_ * 9;            // 2304  (f' = k*256 + c)
constexpr int N_   = B_ * HW_;          // 16384

// Scratch
__device__ __align__(1024) float  g_xt[(size_t)B_ * HW_ * C_];   // NHWC 16.8MB
__device__ __align__(1024) float  g_wt[(size_t)Co_ * F_];        // [co][k*256+c]
__device__ __align__(1024) int4   g_idx[(size_t)N_ * 9];         // corner elem offsets
__device__ __align__(1024) float4 g_wgt[(size_t)N_ * 9];         // bilinear weights

// ---------------------------------------------------------------------------
// Helpers
// ---------------------------------------------------------------------------
__device__ __forceinline__ uint32_t smem_u32(const void* p) {
    uint32_t a;
    asm("{ .reg .u64 t; cvta.to.shared.u64 t, %1; cvt.u32.u64 %0, t; }" : "=r"(a) : "l"(p));
    return a;
}
__device__ __forceinline__ float to_tf32(float x) {
    uint32_t y;
    asm("cvt.rna.tf32.f32 %0, %1;" : "=r"(y) : "f"(x));
    return __uint_as_float(y);
}
__device__ __forceinline__ void cp_async16(uint32_t dst, const void* src) {
    asm volatile("cp.async.cg.shared.global [%0], [%1], 16;" :: "r"(dst), "l"(src));
}
#define CP_COMMIT() asm volatile("cp.async.commit_group;" ::: "memory")
#define CP_WAIT1()  asm volatile("cp.async.wait_group 1;" ::: "memory")

#define BAR_SYNC(id)   asm volatile("bar.sync %0, %1;"   :: "r"(id), "r"(384) : "memory")
#define BAR_ARRIVE(id) asm volatile("bar.arrive %0, %1;" :: "r"(id), "r"(384) : "memory")

#define LDSM_X4(r0, r1, r2, r3, addr)                                          \
    asm volatile("ldmatrix.sync.aligned.m8n8.x4.shared.b16 {%0,%1,%2,%3}, [%4];" \
                 : "=r"(r0), "=r"(r1), "=r"(r2), "=r"(r3) : "r"(addr))

#define MMA_TF32(d, a, b0, b1)                                                 \
    asm volatile("mma.sync.aligned.m16n8k8.row.col.f32.tf32.tf32.f32 "         \
                 "{%0,%1,%2,%3},{%4,%5,%6,%7},{%8,%9},{%0,%1,%2,%3};"          \
                 : "+f"((d)[0]), "+f"((d)[1]), "+f"((d)[2]), "+f"((d)[3])      \
                 : "r"((a)[0]), "r"((a)[1]), "r"((a)[2]), "r"((a)[3]),         \
                   "r"(b0), "r"(b1))

// ---------------------------------------------------------------------------
// Kernel 1: x NCHW -> NHWC
// ---------------------------------------------------------------------------
__global__ __launch_bounds__(256) void transpose_x(const float* __restrict__ x,
                                                   float* __restrict__ xt) {
    __shared__ float t[32][33];
    int b = blockIdx.z, c0 = blockIdx.y * 32, l0 = blockIdx.x * 32;
    int tx = threadIdx.x & 31, ty = threadIdx.x >> 5;
    const float* xb = x + ((size_t)b * C_ + c0) * HW_;
    #pragma unroll
    for (int j = 0; j < 32; j += 8)
        t[ty + j][tx] = xb[(size_t)(ty + j) * HW_ + l0 + tx];
    __syncthreads();
    float* xo = xt + ((size_t)b * HW_ + l0) * C_;
    #pragma unroll
    for (int j = 0; j < 32; j += 8)
        xo[(size_t)(ty + j) * C_ + c0 + tx] = t[tx][ty + j];
}

// ---------------------------------------------------------------------------
// Kernel 2: weight [co][c][k] -> W_t [co][k*256+c], tf32-rounded
// ---------------------------------------------------------------------------
__global__ __launch_bounds__(256) void transpose_w(const float* __restrict__ w,
                                                   float* __restrict__ wt) {
    int co = blockIdx.x;
    const float* wi = w + (size_t)co * F_;
    float* wo = wt + (size_t)co * F_;
    for (int i = threadIdx.x; i < F_; i += 256) {
        int c = i / 9, kk = i % 9;
        wo[kk * 256 + c] = to_tf32(wi[i]);
    }
}

// ---------------------------------------------------------------------------
// Kernel 3: precompute bilinear corner offsets and weights per (n, k)
// ---------------------------------------------------------------------------
__global__ __launch_bounds__(256) void prep_off(const float* __restrict__ off,
                                                int4* __restrict__ gidx,
                                                float4* __restrict__ gwgt) {
    int g = blockIdx.x * 256 + threadIdx.x;     // n*9 + k
    if (g >= N_ * 9) return;
    int n = g / 9, k = g - n * 9;
    int b = n >> 12, p = n & 4095;
    int ho = p >> 6, wo = p & 63;
    int ki = k / 3, kj = k - ki * 3;

    float sy = off[((size_t)(b * 18 + 2 * k))     * HW_ + p] + (float)(ho - 1 + ki);
    float sx = off[((size_t)(b * 18 + 2 * k + 1)) * HW_ + p] + (float)(wo - 1 + kj);

    float y0f = floorf(sy), x0f = floorf(sx);
    float dy = sy - y0f, dx = sx - x0f;
    int y0 = (int)y0f, x0 = (int)x0f, y1 = y0 + 1, x1 = x0 + 1;
    bool vy0 = (y0 >= 0) & (y0 < H_), vy1 = (y1 >= 0) & (y1 < H_);
    bool vx0 = (x0 >= 0) & (x0 < W_), vx1 = (x1 >= 0) & (x1 < W_);

    float4 wv;
    wv.x = (1.f - dy) * (1.f - dx) * (float)(vy0 && vx0);
    wv.y = (1.f - dy) * dx         * (float)(vy0 && vx1);
    wv.z = dy * (1.f - dx)         * (float)(vy1 && vx0);
    wv.w = dy * dx                 * (float)(vy1 && vx1);

    int y0c = min(max(y0, 0), H_ - 1), y1c = min(max(y1, 0), H_ - 1);
    int x0c = min(max(x0, 0), W_ - 1), x1c = min(max(x1, 0), W_ - 1);
    int base = b * HW_;
    int4 iv;
    iv.x = (base + y0c * W_ + x0c) * C_;
    iv.y = (base + y0c * W_ + x1c) * C_;
    iv.z = (base + y1c * W_ + x0c) * C_;
    iv.w = (base + y1c * W_ + x1c) * C_;

    gidx[g] = iv;
    gwgt[g] = wv;
}

// ---------------------------------------------------------------------------
// Kernel 4: warp-specialized fused im2col + tf32 GEMM.
// CTA tile: M=256 x N=128, KCH=32, 3-stage ring (48KB) + 36KB smem tables.
// Warps 0-7 (consumers): LDSM + MMA, AND issue-and-forget cp.async of the A
//   (weight) tile two chunks ahead (wait_group 1 + bar.sync give readiness
//   and cross-thread visibility; issue after the bar avoids WAR on the stage).
// Warps 8-11 (producers): PURE bilinear gather (smem tables) -> STS B.
// Named barriers (count 384): full[s] = 1+s, empty[s] = 4+s.
// ---------------------------------------------------------------------------
constexpr int KCH    = 32;
constexpr int CHUNKS = F_ / KCH;           // 72
constexpr int A_STG  = 256 * KCH * 4;      // 32KB
constexpr int B_OFF  = A_STG;
constexpr int STG_SZ = A_STG + 128 * KCH * 4;   // 48KB
constexpr int STAGES = 3;
constexpr int TBL_OFF = STAGES * STG_SZ;        // 144KB
constexpr int GEMM_SMEM = TBL_OFF + 128 * 9 * 32;   // +36KB = 180KB

__global__ __launch_bounds__(384, 1) void gemm_ws(const float* __restrict__ Wt,
                                                  const float* __restrict__ xt,
                                                  const int4* __restrict__ gidx,
                                                  const float4* __restrict__ gwgt,
                                                  float* __restrict__ out) {
    extern __shared__ char smem[];
    uint32_t sb = smem_u32(smem);
    int tid = threadIdx.x, lane = tid & 31;
    int n0 = blockIdx.x * 128;

    // Cooperative table load: 128 rows x 9 taps, 32B each (iv, wv).
    for (int e = tid; e < 128 * 9; e += 384) {
        int gi = n0 * 9 + e;
        *(int4*)(smem + TBL_OFF + e * 32)        = gidx[gi];
        *(float4*)(smem + TBL_OFF + e * 32 + 16) = gwgt[gi];
    }
    __syncthreads();

    if (tid < 256) {
        // ================= CONSUMERS =================
        int warp = tid >> 5;
        int wm = warp & 3, wn = warp >> 2;    // 4x2 warp grid, 64x64 tiles
        int sel = lane >> 3, row_in = lane & 7;

        // Per-thread constant pieces of the A cp.async addressing.
        int arow0 = tid >> 3, ac16 = tid & 7;
        uint32_t adst0 = (uint32_t)(arow0 * 128 +
                                    ((ac16 * 16) ^ ((arow0 & 7) << 4)));
        const float* asrc0 = Wt + (size_t)arow0 * F_ + ac16 * 4;

        uint32_t aoff[4], ax[4];
        #pragma unroll
        for (int f = 0; f < 4; f++) {
            int m = wm * 64 + f * 16 + (sel & 1) * 8 + row_in;
            aoff[f] = (uint32_t)(m * 128);
            ax[f]   = (uint32_t)(((m & 7) << 4) ^ ((sel >> 1) * 16));
        }
        uint32_t boff[4], bx[4];
        #pragma unroll
        for (int g = 0; g < 4; g++) {
            int n = wn * 64 + g * 16 + (sel >> 1) * 8 + row_in;
            boff[g] = (uint32_t)(B_OFF + n * 128);
            bx[g]   = (uint32_t)(((n & 7) << 4) ^ ((sel & 1) * 16));
        }

        float acc[4][8][4];
        #pragma unroll
        for (int f = 0; f < 4; f++)
            #pragma unroll
            for (int j = 0; j < 8; j++)
                #pragma unroll
                for (int q = 0; q < 4; q++) acc[f][j][q] = 0.f;

        // Prologue: A(0) -> stage 0, A(1) -> stage 1.
        #pragma unroll
        for (int it = 0; it < 8; it++)
            cp_async16(sb + adst0 + it * 4096, asrc0 + (size_t)it * 32 * F_);
        CP_COMMIT();
        #pragma unroll
        for (int it = 0; it < 8; it++)
            cp_async16(sb + STG_SZ + adst0 + it * 4096,
                       asrc0 + (size_t)it * 32 * F_ + KCH);
        CP_COMMIT();

        int s = 0;
        for (int i = 0; i < CHUNKS; i++) {
            uint32_t slot = sb + s * STG_SZ;
            CP_WAIT1();                           // A(i) landed (this thread)
            BAR_SYNC(1 + s);                      // B(i) ready; visibility + WAR

            int j = i + 2;                        // prefetch A(i+2)
            if (j < CHUNKS) {
                int t2 = j - (j / 3) * 3;         // j % 3
                uint32_t dst = sb + t2 * STG_SZ + adst0;
                const float* src = asrc0 + j * KCH;
                #pragma unroll
                for (int it = 0; it < 8; it++)
                    cp_async16(dst + it * 4096, src + (size_t)it * 32 * F_);
            }
            CP_COMMIT();

            #pragma unroll
            for (int ks = 0; ks < 4; ks++) {
                uint32_t kb = ks * 32;
                uint32_t a[4][4], bb[4][4];
                #pragma unroll
                for (int f = 0; f < 4; f++)
                    LDSM_X4(a[f][0], a[f][1], a[f][2], a[f][3],
                            slot + aoff[f] + (kb ^ ax[f]));
                #pragma unroll
                for (int g = 0; g < 4; g++)
                    LDSM_X4(bb[g][0], bb[g][1], bb[g][2], bb[g][3],
                            slot + boff[g] + (kb ^ bx[g]));
                #pragma unroll
                for (int f = 0; f < 4; f++)
                    #pragma unroll
                    for (int j2 = 0; j2 < 8; j2++)
                        MMA_TF32(acc[f][j2], a[f],
                                 bb[j2 >> 1][(j2 & 1) * 2], bb[j2 >> 1][(j2 & 1) * 2 + 1]);
            }
            BAR_ARRIVE(4 + s);                    // signal empty[s]
            s = (s == 2) ? 0 : s + 1;
        }

        // Epilogue
        int tig = lane & 3, gid = lane >> 2;
        int b = n0 >> 12;
        int pbase = (n0 & 4095) + wn * 64;
        #pragma unroll
        for (int f = 0; f < 4; f++) {
            #pragma unroll
            for (int j = 0; j < 8; j++) {
                int co = wm * 64 + f * 16 + gid;
                int p  = pbase + j * 8 + tig * 2;
                float* o0 = out + ((size_t)(b * Co_ + co)) * HW_ + p;
                *(float2*)o0 = make_float2(acc[f][j][0], acc[f][j][1]);
                *(float2*)(o0 + (size_t)8 * HW_) = make_float2(acc[f][j][2], acc[f][j][3]);
            }
        }
    } else {
        // ========== PRODUCERS (4 warps, 128 threads): pure B gather ==========
        int pt   = tid - 256;                     // 0..127
        int prow = pt >> 3;                       // 0..15
        int pc16 = pt & 7;                        // 0..7

        int s = 0;
        for (int kk = 0; kk < 9; kk++) {
            for (int cc = 0; cc < 8; cc++) {
                int i = kk * 8 + cc;
                if (i >= STAGES) BAR_SYNC(4 + s); // wait empty[s]

                // Single batch: all 32 corner LDGs in flight.
                int c = cc * 32 + pc16 * 4;
                float4 v[8][4];
                #pragma unroll
                for (int j = 0; j < 8; j++) {
                    int row = prow + j * 16;
                    int4 iv = *(const int4*)(smem + TBL_OFF + (row * 9 + kk) * 32);
                    v[j][0] = *(const float4*)(xt + iv.x + c);
                    v[j][1] = *(const float4*)(xt + iv.y + c);
                    v[j][2] = *(const float4*)(xt + iv.z + c);
                    v[j][3] = *(const float4*)(xt + iv.w + c);
                }
                char* bslot = smem + s * STG_SZ + B_OFF;
                uint32_t sxor = (uint32_t)((pc16 * 16) ^ ((prow & 7) << 4));
                #pragma unroll
                for (int j = 0; j < 8; j++) {
                    int row = prow + j * 16;
                    float4 wv = *(const float4*)(smem + TBL_OFF +
                                                 (row * 9 + kk) * 32 + 16);
                    float4 r;
                    r.x = to_tf32(wv.x * v[j][0].x + wv.y * v[j][1].x +
                                  wv.z * v[j][2].x + wv.w * v[j][3].x);
                    r.y = to_tf32(wv.x * v[j][0].y + wv.y * v[j][1].y +
                                  wv.z * v[j][2].y + wv.w * v[j][3].y);
                    r.z = to_tf32(wv.x * v[j][0].z + wv.y * v[j][1].z +
                                  wv.z * v[j][2].z + wv.w * v[j][3].z);
                    r.w = to_tf32(wv.x * v[j][0].w + wv.y * v[j][1].w +
                                  wv.z * v[j][2].w + wv.w * v[j][3].w);
                    *(float4*)(bslot + row * 128 + sxor) = r;
                }

                BAR_ARRIVE(1 + s);                // signal full[s]
                s = (s == 2) ? 0 : s + 1;
            }
        }
    }
}

// ---------------------------------------------------------------------------
extern "C" void kernel_launch(void* const* d_in, const int* in_sizes, int n_in,
                              void* d_out, int out_size) {
    const float* x      = (const float*)d_in[0];
    const float* offset = (const float*)d_in[1];
    const float* weight = (const float*)d_in[2];
    float* out = (float*)d_out;

    float *xt, *wt;
    int4* gidx;
    float4* gwgt;
    cudaGetSymbolAddress((void**)&xt, g_xt);
    cudaGetSymbolAddress((void**)&wt, g_wt);
    cudaGetSymbolAddress((void**)&gidx, g_idx);
    cudaGetSymbolAddress((void**)&gwgt, g_wgt);

    cudaFuncSetAttribute(gemm_ws, cudaFuncAttributeMaxDynamicSharedMemorySize, GEMM_SMEM);

    {
        dim3 grid(HW_ / 32, C_ / 32, B_);
        transpose_x<<<grid, 256>>>(x, xt);
    }
    transpose_w<<<Co_, 256>>>(weight, wt);
    prep_off<<<(N_ * 9 + 255) / 256, 256>>>(offset, gidx, gwgt);
    gemm_ws<<<N_ / 128, 384, GEMM_SMEM>>>(wt, xt, gidx, gwgt, out);
}

// round 14
// speedup vs baseline: 1.5250x; 1.5250x over previous
#include <cuda_runtime.h>
#include <cuda_fp16.h>
#include <cstdint>

// ---------------------------------------------------------------------------
// Problem constants
// ---------------------------------------------------------------------------
constexpr int B_   = 4;
constexpr int C_   = 256;
constexpr int H_   = 64;
constexpr int W_   = 64;
constexpr int Co_  = 256;
constexpr int HW_  = 64 * 64;           // 4096
constexpr int F_   = C_ * 9;            // 2304  (f' = k*256 + c)
constexpr int N_   = B_ * HW_;          // 16384

// Scratch
__device__ __align__(1024) float  g_xt[(size_t)B_ * HW_ * C_];   // NHWC 16.8MB
__device__ __align__(1024) __half g_wt[(size_t)Co_ * F_];        // fp16 [co][k*256+c]
__device__ __align__(1024) int4   g_idx[(size_t)N_ * 9];         // corner elem offsets
__device__ __align__(1024) float4 g_wgt[(size_t)N_ * 9];         // bilinear weights

// ---------------------------------------------------------------------------
// Helpers
// ---------------------------------------------------------------------------
__device__ __forceinline__ uint32_t smem_u32(const void* p) {
    uint32_t a;
    asm("{ .reg .u64 t; cvta.to.shared.u64 t, %1; cvt.u32.u64 %0, t; }" : "=r"(a) : "l"(p));
    return a;
}
__device__ __forceinline__ void cp_async16(uint32_t dst, const void* src) {
    asm volatile("cp.async.cg.shared.global [%0], [%1], 16;" :: "r"(dst), "l"(src));
}
#define CP_COMMIT() asm volatile("cp.async.commit_group;" ::: "memory")
#define CP_WAIT1()  asm volatile("cp.async.wait_group 1;" ::: "memory")

#define BAR_SYNC(id)   asm volatile("bar.sync %0, %1;"   :: "r"(id), "r"(384) : "memory")
#define BAR_ARRIVE(id) asm volatile("bar.arrive %0, %1;" :: "r"(id), "r"(384) : "memory")

#define LDSM_X4(r0, r1, r2, r3, addr)                                          \
    asm volatile("ldmatrix.sync.aligned.m8n8.x4.shared.b16 {%0,%1,%2,%3}, [%4];" \
                 : "=r"(r0), "=r"(r1), "=r"(r2), "=r"(r3) : "r"(addr))

#define MMA_F16(d, a, b0, b1)                                                  \
    asm volatile("mma.sync.aligned.m16n8k16.row.col.f32.f16.f16.f32 "          \
                 "{%0,%1,%2,%3},{%4,%5,%6,%7},{%8,%9},{%0,%1,%2,%3};"          \
                 : "+f"((d)[0]), "+f"((d)[1]), "+f"((d)[2]), "+f"((d)[3])      \
                 : "r"((a)[0]), "r"((a)[1]), "r"((a)[2]), "r"((a)[3]),         \
                   "r"(b0), "r"(b1))

// ---------------------------------------------------------------------------
// Kernel 1: x NCHW -> NHWC
// ---------------------------------------------------------------------------
__global__ __launch_bounds__(256) void transpose_x(const float* __restrict__ x,
                                                   float* __restrict__ xt) {
    __shared__ float t[32][33];
    int b = blockIdx.z, c0 = blockIdx.y * 32, l0 = blockIdx.x * 32;
    int tx = threadIdx.x & 31, ty = threadIdx.x >> 5;
    const float* xb = x + ((size_t)b * C_ + c0) * HW_;
    #pragma unroll
    for (int j = 0; j < 32; j += 8)
        t[ty + j][tx] = xb[(size_t)(ty + j) * HW_ + l0 + tx];
    __syncthreads();
    float* xo = xt + ((size_t)b * HW_ + l0) * C_;
    #pragma unroll
    for (int j = 0; j < 32; j += 8)
        xo[(size_t)(ty + j) * C_ + c0 + tx] = t[tx][ty + j];
}

// ---------------------------------------------------------------------------
// Kernel 2: weight [co][c][k] -> W_t [co][k*256+c], fp16
// ---------------------------------------------------------------------------
__global__ __launch_bounds__(256) void transpose_w(const float* __restrict__ w,
                                                   __half* __restrict__ wt) {
    int co = blockIdx.x;
    const float* wi = w + (size_t)co * F_;
    __half* wo = wt + (size_t)co * F_;
    for (int i = threadIdx.x; i < F_; i += 256) {
        int c = i / 9, kk = i % 9;
        wo[kk * 256 + c] = __float2half_rn(wi[i]);
    }
}

// ---------------------------------------------------------------------------
// Kernel 3: precompute bilinear corner offsets and weights per (n, k)
// ---------------------------------------------------------------------------
__global__ __launch_bounds__(256) void prep_off(const float* __restrict__ off,
                                                int4* __restrict__ gidx,
                                                float4* __restrict__ gwgt) {
    int g = blockIdx.x * 256 + threadIdx.x;     // n*9 + k
    if (g >= N_ * 9) return;
    int n = g / 9, k = g - n * 9;
    int b = n >> 12, p = n & 4095;
    int ho = p >> 6, wo = p & 63;
    int ki = k / 3, kj = k - ki * 3;

    float sy = off[((size_t)(b * 18 + 2 * k))     * HW_ + p] + (float)(ho - 1 + ki);
    float sx = off[((size_t)(b * 18 + 2 * k + 1)) * HW_ + p] + (float)(wo - 1 + kj);

    float y0f = floorf(sy), x0f = floorf(sx);
    float dy = sy - y0f, dx = sx - x0f;
    int y0 = (int)y0f, x0 = (int)x0f, y1 = y0 + 1, x1 = x0 + 1;
    bool vy0 = (y0 >= 0) & (y0 < H_), vy1 = (y1 >= 0) & (y1 < H_);
    bool vx0 = (x0 >= 0) & (x0 < W_), vx1 = (x1 >= 0) & (x1 < W_);

    float4 wv;
    wv.x = (1.f - dy) * (1.f - dx) * (float)(vy0 && vx0);
    wv.y = (1.f - dy) * dx         * (float)(vy0 && vx1);
    wv.z = dy * (1.f - dx)         * (float)(vy1 && vx0);
    wv.w = dy * dx                 * (float)(vy1 && vx1);

    int y0c = min(max(y0, 0), H_ - 1), y1c = min(max(y1, 0), H_ - 1);
    int x0c = min(max(x0, 0), W_ - 1), x1c = min(max(x1, 0), W_ - 1);
    int base = b * HW_;
    int4 iv;
    iv.x = (base + y0c * W_ + x0c) * C_;
    iv.y = (base + y0c * W_ + x1c) * C_;
    iv.z = (base + y1c * W_ + x0c) * C_;
    iv.w = (base + y1c * W_ + x1c) * C_;

    gidx[g] = iv;
    gwgt[g] = wv;
}

// ---------------------------------------------------------------------------
// Kernel 4: warp-specialized fused im2col + FP16 GEMM (m16n8k16, fp32 acc).
// CTA tile: M=256 x N=128, KCH=64 fp16 elems (128B rows), 3-stage ring
// (48KB each) + 36KB smem tables. CHUNKS=36.
// Warps 0-7 (consumers): LDSM + MMA + issue-and-forget cp.async A prefetch.
// Warps 8-11 (producers): pure bilinear gather (fp32) -> half2 pack -> STS B.
// Named barriers (count 384): full[s] = 1+s, empty[s] = 4+s.
// ---------------------------------------------------------------------------
constexpr int KCH    = 64;                 // fp16 k-elements per chunk
constexpr int CHUNKS = F_ / KCH;           // 36
constexpr int A_STG  = 256 * 128;          // 32KB (256 rows x 128B)
constexpr int B_OFF  = A_STG;
constexpr int STG_SZ = A_STG + 128 * 128;  // 48KB
constexpr int STAGES = 3;
constexpr int TBL_OFF = STAGES * STG_SZ;        // 144KB
constexpr int GEMM_SMEM = TBL_OFF + 128 * 9 * 32;   // +36KB = 180KB

__global__ __launch_bounds__(384, 1) void gemm_ws(const __half* __restrict__ Wt,
                                                  const float* __restrict__ xt,
                                                  const int4* __restrict__ gidx,
                                                  const float4* __restrict__ gwgt,
                                                  float* __restrict__ out) {
    extern __shared__ char smem[];
    uint32_t sb = smem_u32(smem);
    int tid = threadIdx.x, lane = tid & 31;
    int n0 = blockIdx.x * 128;

    // Cooperative table load: 128 rows x 9 taps, 32B each (iv, wv).
    for (int e = tid; e < 128 * 9; e += 384) {
        int gi = n0 * 9 + e;
        *(int4*)(smem + TBL_OFF + e * 32)        = gidx[gi];
        *(float4*)(smem + TBL_OFF + e * 32 + 16) = gwgt[gi];
    }
    __syncthreads();

    if (tid < 256) {
        // ================= CONSUMERS =================
        int warp = tid >> 5;
        int wm = warp & 3, wn = warp >> 2;    // 4x2 warp grid, 64x64 tiles
        int sel = lane >> 3, row_in = lane & 7;

        // A cp.async addressing: u = tid + it*256 -> row = (tid>>3)+it*32.
        int arow0 = tid >> 3, ac16 = tid & 7;
        uint32_t adst0 = (uint32_t)(arow0 * 128 +
                                    ((ac16 * 16) ^ ((arow0 & 7) << 4)));
        const __half* asrc0 = Wt + (size_t)arow0 * F_ + ac16 * 8;

        uint32_t aoff[4], ax[4];
        #pragma unroll
        for (int f = 0; f < 4; f++) {
            int m = wm * 64 + f * 16 + (sel & 1) * 8 + row_in;
            aoff[f] = (uint32_t)(m * 128);
            ax[f]   = (uint32_t)(((m & 7) << 4) ^ ((sel >> 1) * 16));
        }
        uint32_t boff[4], bx[4];
        #pragma unroll
        for (int g = 0; g < 4; g++) {
            int n = wn * 64 + g * 16 + (sel >> 1) * 8 + row_in;
            boff[g] = (uint32_t)(B_OFF + n * 128);
            bx[g]   = (uint32_t)(((n & 7) << 4) ^ ((sel & 1) * 16));
        }

        float acc[4][8][4];
        #pragma unroll
        for (int f = 0; f < 4; f++)
            #pragma unroll
            for (int j = 0; j < 8; j++)
                #pragma unroll
                for (int q = 0; q < 4; q++) acc[f][j][q] = 0.f;

        // Prologue: A(0) -> stage 0, A(1) -> stage 1.
        #pragma unroll
        for (int it = 0; it < 8; it++)
            cp_async16(sb + adst0 + it * 4096, asrc0 + (size_t)it * 32 * F_);
        CP_COMMIT();
        #pragma unroll
        for (int it = 0; it < 8; it++)
            cp_async16(sb + STG_SZ + adst0 + it * 4096,
                       asrc0 + (size_t)it * 32 * F_ + KCH);
        CP_COMMIT();

        int s = 0;
        for (int i = 0; i < CHUNKS; i++) {
            uint32_t slot = sb + s * STG_SZ;
            CP_WAIT1();                           // A(i) landed (this thread)
            BAR_SYNC(1 + s);                      // B(i) ready; visibility + WAR

            int j = i + 2;                        // prefetch A(i+2)
            if (j < CHUNKS) {
                int t2 = j - (j / 3) * 3;         // j % 3
                uint32_t dst = sb + t2 * STG_SZ + adst0;
                const __half* src = asrc0 + j * KCH;
                #pragma unroll
                for (int it = 0; it < 8; it++)
                    cp_async16(dst + it * 4096, src + (size_t)it * 32 * F_);
            }
            CP_COMMIT();

            #pragma unroll
            for (int ks = 0; ks < 4; ks++) {      // k16 per iteration
                uint32_t kb = ks * 32;            // 32B = 16 fp16
                uint32_t a[4][4], bb[4][4];
                #pragma unroll
                for (int f = 0; f < 4; f++)
                    LDSM_X4(a[f][0], a[f][1], a[f][2], a[f][3],
                            slot + aoff[f] + (kb ^ ax[f]));
                #pragma unroll
                for (int g = 0; g < 4; g++)
                    LDSM_X4(bb[g][0], bb[g][1], bb[g][2], bb[g][3],
                            slot + boff[g] + (kb ^ bx[g]));
                #pragma unroll
                for (int f = 0; f < 4; f++)
                    #pragma unroll
                    for (int j2 = 0; j2 < 8; j2++)
                        MMA_F16(acc[f][j2], a[f],
                                bb[j2 >> 1][(j2 & 1) * 2], bb[j2 >> 1][(j2 & 1) * 2 + 1]);
            }
            BAR_ARRIVE(4 + s);                    // signal empty[s]
            s = (s == 2) ? 0 : s + 1;
        }

        // Epilogue
        int tig = lane & 3, gid = lane >> 2;
        int b = n0 >> 12;
        int pbase = (n0 & 4095) + wn * 64;
        #pragma unroll
        for (int f = 0; f < 4; f++) {
            #pragma unroll
            for (int j = 0; j < 8; j++) {
                int co = wm * 64 + f * 16 + gid;
                int p  = pbase + j * 8 + tig * 2;
                float* o0 = out + ((size_t)(b * Co_ + co)) * HW_ + p;
                *(float2*)o0 = make_float2(acc[f][j][0], acc[f][j][1]);
                *(float2*)(o0 + (size_t)8 * HW_) = make_float2(acc[f][j][2], acc[f][j][3]);
            }
        }
    } else {
        // ========== PRODUCERS (4 warps, 128 threads): pure B gather ==========
        int pt   = tid - 256;                     // 0..127
        int prow = pt >> 3;                       // 0..15
        int pc16 = pt & 7;                        // 0..7  (8 fp16 channels each)

        int s = 0;
        for (int kk = 0; kk < 9; kk++) {
            for (int cc = 0; cc < 4; cc++) {
                int i = kk * 4 + cc;
                if (i >= STAGES) BAR_SYNC(4 + s); // wait empty[s]

                int cb = cc * 64 + pc16 * 8;      // fp32 channel base
                char* bslot = smem + s * STG_SZ + B_OFF;
                uint32_t sxor = (uint32_t)((pc16 * 16) ^ ((prow & 7) << 4));

                #pragma unroll
                for (int b2 = 0; b2 < 2; b2++) {
                    // Batch: 4 rows x 8 float4 corner loads all in flight.
                    float4 v[4][8];
                    #pragma unroll
                    for (int j = 0; j < 4; j++) {
                        int row = prow + (b2 * 4 + j) * 16;
                        int4 iv = *(const int4*)(smem + TBL_OFF +
                                                 (row * 9 + kk) * 32);
                        v[j][0] = *(const float4*)(xt + iv.x + cb);
                        v[j][1] = *(const float4*)(xt + iv.x + cb + 4);
                        v[j][2] = *(const float4*)(xt + iv.y + cb);
                        v[j][3] = *(const float4*)(xt + iv.y + cb + 4);
                        v[j][4] = *(const float4*)(xt + iv.z + cb);
                        v[j][5] = *(const float4*)(xt + iv.z + cb + 4);
                        v[j][6] = *(const float4*)(xt + iv.w + cb);
                        v[j][7] = *(const float4*)(xt + iv.w + cb + 4);
                    }
                    #pragma unroll
                    for (int j = 0; j < 4; j++) {
                        int row = prow + (b2 * 4 + j) * 16;
                        float4 wv = *(const float4*)(smem + TBL_OFF +
                                                     (row * 9 + kk) * 32 + 16);
                        float lo0 = wv.x*v[j][0].x + wv.y*v[j][2].x + wv.z*v[j][4].x + wv.w*v[j][6].x;
                        float lo1 = wv.x*v[j][0].y + wv.y*v[j][2].y + wv.z*v[j][4].y + wv.w*v[j][6].y;
                        float lo2 = wv.x*v[j][0].z + wv.y*v[j][2].z + wv.z*v[j][4].z + wv.w*v[j][6].z;
                        float lo3 = wv.x*v[j][0].w + wv.y*v[j][2].w + wv.z*v[j][4].w + wv.w*v[j][6].w;
                        float hi0 = wv.x*v[j][1].x + wv.y*v[j][3].x + wv.z*v[j][5].x + wv.w*v[j][7].x;
                        float hi1 = wv.x*v[j][1].y + wv.y*v[j][3].y + wv.z*v[j][5].y + wv.w*v[j][7].y;
                        float hi2 = wv.x*v[j][1].z + wv.y*v[j][3].z + wv.z*v[j][5].z + wv.w*v[j][7].z;
                        float hi3 = wv.x*v[j][1].w + wv.y*v[j][3].w + wv.z*v[j][5].w + wv.w*v[j][7].w;
                        __half2 h0 = __floats2half2_rn(lo0, lo1);
                        __half2 h1 = __floats2half2_rn(lo2, lo3);
                        __half2 h2 = __floats2half2_rn(hi0, hi1);
                        __half2 h3 = __floats2half2_rn(hi2, hi3);
                        uint4 pk;
                        pk.x = *(uint32_t*)&h0;  pk.y = *(uint32_t*)&h1;
                        pk.z = *(uint32_t*)&h2;  pk.w = *(uint32_t*)&h3;
                        *(uint4*)(bslot + row * 128 + sxor) = pk;
                    }
                }

                BAR_ARRIVE(1 + s);                // signal full[s]
                s = (s == 2) ? 0 : s + 1;
            }
        }
    }
}

// ---------------------------------------------------------------------------
extern "C" void kernel_launch(void* const* d_in, const int* in_sizes, int n_in,
                              void* d_out, int out_size) {
    const float* x      = (const float*)d_in[0];
    const float* offset = (const float*)d_in[1];
    const float* weight = (const float*)d_in[2];
    float* out = (float*)d_out;

    float* xt;
    __half* wt;
    int4* gidx;
    float4* gwgt;
    cudaGetSymbolAddress((void**)&xt, g_xt);
    cudaGetSymbolAddress((void**)&wt, g_wt);
    cudaGetSymbolAddress((void**)&gidx, g_idx);
    cudaGetSymbolAddress((void**)&gwgt, g_wgt);

    cudaFuncSetAttribute(gemm_ws, cudaFuncAttributeMaxDynamicSharedMemorySize, GEMM_SMEM);

    {
        dim3 grid(HW_ / 32, C_ / 32, B_);
        transpose_x<<<grid, 256>>>(x, xt);
    }
    transpose_w<<<Co_, 256>>>(weight, wt);
    prep_off<<<(N_ * 9 + 255) / 256, 256>>>(offset, gidx, gwgt);
    gemm_ws<<<N_ / 128, 384, GEMM_SMEM>>>(wt, xt, gidx, gwgt, out);
}

// round 15
// speedup vs baseline: 1.6987x; 1.1139x over previous
#include <cuda_runtime.h>
#include <cuda_fp16.h>
#include <cstdint>

// ---------------------------------------------------------------------------
// Problem constants
// ---------------------------------------------------------------------------
constexpr int B_   = 4;
constexpr int C_   = 256;
constexpr int H_   = 64;
constexpr int W_   = 64;
constexpr int Co_  = 256;
constexpr int HW_  = 64 * 64;           // 4096
constexpr int F_   = C_ * 9;            // 2304  (f' = k*256 + c)
constexpr int N_   = B_ * HW_;          // 16384

// Scratch
__device__ __align__(1024) __half g_xt[(size_t)B_ * HW_ * C_];   // NHWC fp16 8.4MB
__device__ __align__(1024) __half g_wt[(size_t)Co_ * F_];        // fp16 [co][k*256+c]
__device__ __align__(1024) int4   g_idx[(size_t)N_ * 9];         // corner elem offsets
__device__ __align__(1024) float4 g_wgt[(size_t)N_ * 9];         // bilinear weights

// ---------------------------------------------------------------------------
// Helpers
// ---------------------------------------------------------------------------
__device__ __forceinline__ uint32_t smem_u32(const void* p) {
    uint32_t a;
    asm("{ .reg .u64 t; cvta.to.shared.u64 t, %1; cvt.u32.u64 %0, t; }" : "=r"(a) : "l"(p));
    return a;
}
__device__ __forceinline__ void cp_async16(uint32_t dst, const void* src) {
    asm volatile("cp.async.cg.shared.global [%0], [%1], 16;" :: "r"(dst), "l"(src));
}
#define CP_COMMIT() asm volatile("cp.async.commit_group;" ::: "memory")
#define CP_WAIT1()  asm volatile("cp.async.wait_group 1;" ::: "memory")

#define BAR_SYNC(id)   asm volatile("bar.sync %0, %1;"   :: "r"(id), "r"(384) : "memory")
#define BAR_ARRIVE(id) asm volatile("bar.arrive %0, %1;" :: "r"(id), "r"(384) : "memory")

#define LDSM_X4(r0, r1, r2, r3, addr)                                          \
    asm volatile("ldmatrix.sync.aligned.m8n8.x4.shared.b16 {%0,%1,%2,%3}, [%4];" \
                 : "=r"(r0), "=r"(r1), "=r"(r2), "=r"(r3) : "r"(addr))

#define MMA_F16(d, a, b0, b1)                                                  \
    asm volatile("mma.sync.aligned.m16n8k16.row.col.f32.f16.f16.f32 "          \
                 "{%0,%1,%2,%3},{%4,%5,%6,%7},{%8,%9},{%0,%1,%2,%3};"          \
                 : "+f"((d)[0]), "+f"((d)[1]), "+f"((d)[2]), "+f"((d)[3])      \
                 : "r"((a)[0]), "r"((a)[1]), "r"((a)[2]), "r"((a)[3]),         \
                   "r"(b0), "r"(b1))

// ---------------------------------------------------------------------------
// Kernel 1: x NCHW (f32) -> NHWC (fp16)
// ---------------------------------------------------------------------------
__global__ __launch_bounds__(256) void transpose_x(const float* __restrict__ x,
                                                   __half* __restrict__ xt) {
    __shared__ float t[32][33];
    int b = blockIdx.z, c0 = blockIdx.y * 32, l0 = blockIdx.x * 32;
    int tx = threadIdx.x & 31, ty = threadIdx.x >> 5;
    const float* xb = x + ((size_t)b * C_ + c0) * HW_;
    #pragma unroll
    for (int j = 0; j < 32; j += 8)
        t[ty + j][tx] = xb[(size_t)(ty + j) * HW_ + l0 + tx];
    __syncthreads();
    __half* xo = xt + ((size_t)b * HW_ + l0) * C_;
    #pragma unroll
    for (int j = 0; j < 32; j += 8)
        xo[(size_t)(ty + j) * C_ + c0 + tx] = __float2half_rn(t[tx][ty + j]);
}

// ---------------------------------------------------------------------------
// Kernel 2: weight [co][c][k] -> W_t [co][k*256+c], fp16
// ---------------------------------------------------------------------------
__global__ __launch_bounds__(256) void transpose_w(const float* __restrict__ w,
                                                   __half* __restrict__ wt) {
    int co = blockIdx.x;
    const float* wi = w + (size_t)co * F_;
    __half* wo = wt + (size_t)co * F_;
    for (int i = threadIdx.x; i < F_; i += 256) {
        int c = i / 9, kk = i % 9;
        wo[kk * 256 + c] = __float2half_rn(wi[i]);
    }
}

// ---------------------------------------------------------------------------
// Kernel 3: precompute bilinear corner offsets and weights per (n, k)
// ---------------------------------------------------------------------------
__global__ __launch_bounds__(256) void prep_off(const float* __restrict__ off,
                                                int4* __restrict__ gidx,
                                                float4* __restrict__ gwgt) {
    int g = blockIdx.x * 256 + threadIdx.x;     // n*9 + k
    if (g >= N_ * 9) return;
    int n = g / 9, k = g - n * 9;
    int b = n >> 12, p = n & 4095;
    int ho = p >> 6, wo = p & 63;
    int ki = k / 3, kj = k - ki * 3;

    float sy = off[((size_t)(b * 18 + 2 * k))     * HW_ + p] + (float)(ho - 1 + ki);
    float sx = off[((size_t)(b * 18 + 2 * k + 1)) * HW_ + p] + (float)(wo - 1 + kj);

    float y0f = floorf(sy), x0f = floorf(sx);
    float dy = sy - y0f, dx = sx - x0f;
    int y0 = (int)y0f, x0 = (int)x0f, y1 = y0 + 1, x1 = x0 + 1;
    bool vy0 = (y0 >= 0) & (y0 < H_), vy1 = (y1 >= 0) & (y1 < H_);
    bool vx0 = (x0 >= 0) & (x0 < W_), vx1 = (x1 >= 0) & (x1 < W_);

    float4 wv;
    wv.x = (1.f - dy) * (1.f - dx) * (float)(vy0 && vx0);
    wv.y = (1.f - dy) * dx         * (float)(vy0 && vx1);
    wv.z = dy * (1.f - dx)         * (float)(vy1 && vx0);
    wv.w = dy * dx                 * (float)(vy1 && vx1);

    int y0c = min(max(y0, 0), H_ - 1), y1c = min(max(y1, 0), H_ - 1);
    int x0c = min(max(x0, 0), W_ - 1), x1c = min(max(x1, 0), W_ - 1);
    int base = b * HW_;
    int4 iv;
    iv.x = (base + y0c * W_ + x0c) * C_;
    iv.y = (base + y0c * W_ + x1c) * C_;
    iv.z = (base + y1c * W_ + x0c) * C_;
    iv.w = (base + y1c * W_ + x1c) * C_;

    gidx[g] = iv;
    gwgt[g] = wv;
}

// ---------------------------------------------------------------------------
// Kernel 4: warp-specialized fused im2col + FP16 GEMM (m16n8k16, fp32 acc).
// CTA tile: M=256 x N=128, KCH=64 fp16 elems (128B rows), 3-stage ring
// (48KB each) + 36KB smem tables. CHUNKS=36.
// Warps 0-7 (consumers): LDSM + MMA + issue-and-forget cp.async A prefetch.
// Warps 8-11 (producers): bilinear gather on FP16 NHWC x (uint4 corner loads,
//   fp32 combine) -> STS B.
// Named barriers (count 384): full[s] = 1+s, empty[s] = 4+s.
// ---------------------------------------------------------------------------
constexpr int KCH    = 64;                 // fp16 k-elements per chunk
constexpr int CHUNKS = F_ / KCH;           // 36
constexpr int A_STG  = 256 * 128;          // 32KB (256 rows x 128B)
constexpr int B_OFF  = A_STG;
constexpr int STG_SZ = A_STG + 128 * 128;  // 48KB
constexpr int STAGES = 3;
constexpr int TBL_OFF = STAGES * STG_SZ;        // 144KB
constexpr int GEMM_SMEM = TBL_OFF + 128 * 9 * 32;   // +36KB = 180KB

__global__ __launch_bounds__(384, 1) void gemm_ws(const __half* __restrict__ Wt,
                                                  const __half* __restrict__ xt,
                                                  const int4* __restrict__ gidx,
                                                  const float4* __restrict__ gwgt,
                                                  float* __restrict__ out) {
    extern __shared__ char smem[];
    uint32_t sb = smem_u32(smem);
    int tid = threadIdx.x, lane = tid & 31;
    int n0 = blockIdx.x * 128;

    // Cooperative table load: 128 rows x 9 taps, 32B each (iv, wv).
    for (int e = tid; e < 128 * 9; e += 384) {
        int gi = n0 * 9 + e;
        *(int4*)(smem + TBL_OFF + e * 32)        = gidx[gi];
        *(float4*)(smem + TBL_OFF + e * 32 + 16) = gwgt[gi];
    }
    __syncthreads();

    if (tid < 256) {
        // ================= CONSUMERS =================
        int warp = tid >> 5;
        int wm = warp & 3, wn = warp >> 2;    // 4x2 warp grid, 64x64 tiles
        int sel = lane >> 3, row_in = lane & 7;

        // A cp.async addressing: u = tid + it*256 -> row = (tid>>3)+it*32.
        int arow0 = tid >> 3, ac16 = tid & 7;
        uint32_t adst0 = (uint32_t)(arow0 * 128 +
                                    ((ac16 * 16) ^ ((arow0 & 7) << 4)));
        const __half* asrc0 = Wt + (size_t)arow0 * F_ + ac16 * 8;

        uint32_t aoff[4], ax[4];
        #pragma unroll
        for (int f = 0; f < 4; f++) {
            int m = wm * 64 + f * 16 + (sel & 1) * 8 + row_in;
            aoff[f] = (uint32_t)(m * 128);
            ax[f]   = (uint32_t)(((m & 7) << 4) ^ ((sel >> 1) * 16));
        }
        uint32_t boff[4], bx[4];
        #pragma unroll
        for (int g = 0; g < 4; g++) {
            int n = wn * 64 + g * 16 + (sel >> 1) * 8 + row_in;
            boff[g] = (uint32_t)(B_OFF + n * 128);
            bx[g]   = (uint32_t)(((n & 7) << 4) ^ ((sel & 1) * 16));
        }

        float acc[4][8][4];
        #pragma unroll
        for (int f = 0; f < 4; f++)
            #pragma unroll
            for (int j = 0; j < 8; j++)
                #pragma unroll
                for (int q = 0; q < 4; q++) acc[f][j][q] = 0.f;

        // Prologue: A(0) -> stage 0, A(1) -> stage 1.
        #pragma unroll
        for (int it = 0; it < 8; it++)
            cp_async16(sb + adst0 + it * 4096, asrc0 + (size_t)it * 32 * F_);
        CP_COMMIT();
        #pragma unroll
        for (int it = 0; it < 8; it++)
            cp_async16(sb + STG_SZ + adst0 + it * 4096,
                       asrc0 + (size_t)it * 32 * F_ + KCH);
        CP_COMMIT();

        int s = 0;
        for (int i = 0; i < CHUNKS; i++) {
            uint32_t slot = sb + s * STG_SZ;
            CP_WAIT1();                           // A(i) landed (this thread)
            BAR_SYNC(1 + s);                      // B(i) ready; visibility + WAR

            int j = i + 2;                        // prefetch A(i+2)
            if (j < CHUNKS) {
                int t2 = j - (j / 3) * 3;         // j % 3
                uint32_t dst = sb + t2 * STG_SZ + adst0;
                const __half* src = asrc0 + j * KCH;
                #pragma unroll
                for (int it = 0; it < 8; it++)
                    cp_async16(dst + it * 4096, src + (size_t)it * 32 * F_);
            }
            CP_COMMIT();

            #pragma unroll
            for (int ks = 0; ks < 4; ks++) {      // k16 per iteration
                uint32_t kb = ks * 32;            // 32B = 16 fp16
                uint32_t a[4][4], bb[4][4];
                #pragma unroll
                for (int f = 0; f < 4; f++)
                    LDSM_X4(a[f][0], a[f][1], a[f][2], a[f][3],
                            slot + aoff[f] + (kb ^ ax[f]));
                #pragma unroll
                for (int g = 0; g < 4; g++)
                    LDSM_X4(bb[g][0], bb[g][1], bb[g][2], bb[g][3],
                            slot + boff[g] + (kb ^ bx[g]));
                #pragma unroll
                for (int f = 0; f < 4; f++)
                    #pragma unroll
                    for (int j2 = 0; j2 < 8; j2++)
                        MMA_F16(acc[f][j2], a[f],
                                bb[j2 >> 1][(j2 & 1) * 2], bb[j2 >> 1][(j2 & 1) * 2 + 1]);
            }
            BAR_ARRIVE(4 + s);                    // signal empty[s]
            s = (s == 2) ? 0 : s + 1;
        }

        // Epilogue
        int tig = lane & 3, gid = lane >> 2;
        int b = n0 >> 12;
        int pbase = (n0 & 4095) + wn * 64;
        #pragma unroll
        for (int f = 0; f < 4; f++) {
            #pragma unroll
            for (int j = 0; j < 8; j++) {
                int co = wm * 64 + f * 16 + gid;
                int p  = pbase + j * 8 + tig * 2;
                float* o0 = out + ((size_t)(b * Co_ + co)) * HW_ + p;
                *(float2*)o0 = make_float2(acc[f][j][0], acc[f][j][1]);
                *(float2*)(o0 + (size_t)8 * HW_) = make_float2(acc[f][j][2], acc[f][j][3]);
            }
        }
    } else {
        // ========== PRODUCERS (4 warps, 128 threads): fp16 B gather ==========
        int pt   = tid - 256;                     // 0..127
        int prow = pt >> 3;                       // 0..15
        int pc16 = pt & 7;                        // 0..7  (8 fp16 channels each)

        int s = 0;
        for (int kk = 0; kk < 9; kk++) {
            for (int cc = 0; cc < 4; cc++) {
                int i = kk * 4 + cc;
                if (i >= STAGES) BAR_SYNC(4 + s); // wait empty[s]

                int cb = cc * 64 + pc16 * 8;      // fp16 channel base
                char* bslot = smem + s * STG_SZ + B_OFF;
                uint32_t sxor = (uint32_t)((pc16 * 16) ^ ((prow & 7) << 4));

                // Single batch: all 8 rows x 4 corner uint4 loads in flight.
                uint4 v[8][4];
                #pragma unroll
                for (int j = 0; j < 8; j++) {
                    int row = prow + j * 16;
                    int4 iv = *(const int4*)(smem + TBL_OFF + (row * 9 + kk) * 32);
                    v[j][0] = *(const uint4*)(xt + iv.x + cb);
                    v[j][1] = *(const uint4*)(xt + iv.y + cb);
                    v[j][2] = *(const uint4*)(xt + iv.z + cb);
                    v[j][3] = *(const uint4*)(xt + iv.w + cb);
                }
                #pragma unroll
                for (int j = 0; j < 8; j++) {
                    int row = prow + j * 16;
                    float4 wv = *(const float4*)(smem + TBL_OFF +
                                                 (row * 9 + kk) * 32 + 16);
                    const __half2* h00 = (const __half2*)&v[j][0];
                    const __half2* h01 = (const __half2*)&v[j][1];
                    const __half2* h10 = (const __half2*)&v[j][2];
                    const __half2* h11 = (const __half2*)&v[j][3];
                    uint4 pk;
                    uint32_t* pko = (uint32_t*)&pk;
                    #pragma unroll
                    for (int g = 0; g < 4; g++) {
                        float2 a0 = __half22float2(h00[g]);
                        float2 a1 = __half22float2(h01[g]);
                        float2 a2 = __half22float2(h10[g]);
                        float2 a3 = __half22float2(h11[g]);
                        float rx = wv.x * a0.x + wv.y * a1.x + wv.z * a2.x + wv.w * a3.x;
                        float ry = wv.x * a0.y + wv.y * a1.y + wv.z * a2.y + wv.w * a3.y;
                        __half2 h = __floats2half2_rn(rx, ry);
                        pko[g] = *(uint32_t*)&h;
                    }
                    *(uint4*)(bslot + row * 128 + sxor) = pk;
                }

                BAR_ARRIVE(1 + s);                // signal full[s]
                s = (s == 2) ? 0 : s + 1;
            }
        }
    }
}

// ---------------------------------------------------------------------------
extern "C" void kernel_launch(void* const* d_in, const int* in_sizes, int n_in,
                              void* d_out, int out_size) {
    const float* x      = (const float*)d_in[0];
    const float* offset = (const float*)d_in[1];
    const float* weight = (const float*)d_in[2];
    float* out = (float*)d_out;

    __half *xt, *wt;
    int4* gidx;
    float4* gwgt;
    cudaGetSymbolAddress((void**)&xt, g_xt);
    cudaGetSymbolAddress((void**)&wt, g_wt);
    cudaGetSymbolAddress((void**)&gidx, g_idx);
    cudaGetSymbolAddress((void**)&gwgt, g_wgt);

    cudaFuncSetAttribute(gemm_ws, cudaFuncAttributeMaxDynamicSharedMemorySize, GEMM_SMEM);

    {
        dim3 grid(HW_ / 32, C_ / 32, B_);
        transpose_x<<<grid, 256>>>(x, xt);
    }
    transpose_w<<<Co_, 256>>>(weight, wt);
    prep_off<<<(N_ * 9 + 255) / 256, 256>>>(offset, gidx, gwgt);
    gemm_ws<<<N_ / 128, 384, GEMM_SMEM>>>(wt, xt, gidx, gwgt, out);
}